// round 4
// baseline (speedup 1.0000x reference)
#include <cuda_runtime.h>
#include <cuda_bf16.h>
#include <math.h>
#include <stdint.h>

#define Bc 4
#define Sc 2048
#define Ec 1024
#define Hc 8
#define Dc 128
#define BSc (Bc*Sc)        // 8192 tokens
#define HDc (Hc*Dc)        // 1024
#define EPSc 1e-5f

// smem staging: 4 tiles (Ah, Al, Bh, Bl), each 128 rows x 32 bf16, row stride 80B
#define RS 80
#define TILE_B (128*RS)            // 10240
#define STAGE_B (4*TILE_B)         // 40960
#define SMEM_DYN (2*STAGE_B)       // 81920

// ---------------- scratch ----------------
__device__ __align__(16) float g_z    [BSc*HDc];
__device__ __align__(16) float g_hln  [BSc*HDc];
__device__ __align__(16) float g_h1   [BSc*HDc];
__device__ __align__(16) float g_sc   [BSc*Hc];
__device__ __align__(16) float g_v    [HDc];
__device__ __align__(16) float g_c    [Hc];
__device__ __align__(16) float g_WezT [Ec*HDc];     // [n=HD][k=E]
__device__ __align__(16) float g_W2T  [Ec*HDc];     // [n=E][k=HD]
__device__ __align__(16) float g_W1T  [Hc*Dc*Dc];   // per head [n][k]

// ---------------- helpers ----------------
__device__ __forceinline__ float warpSum(float v){
    #pragma unroll
    for (int o = 16; o; o >>= 1) v += __shfl_xor_sync(0xffffffffu, v, o);
    return v;
}
__device__ __forceinline__ void warpRed4(float& a, float& b, float& c, float& d){
    #pragma unroll
    for (int o = 16; o; o >>= 1){
        a += __shfl_xor_sync(0xffffffffu, a, o);
        b += __shfl_xor_sync(0xffffffffu, b, o);
        c += __shfl_xor_sync(0xffffffffu, c, o);
        d += __shfl_xor_sync(0xffffffffu, d, o);
    }
}
__device__ __forceinline__ uint32_t smem_u32(const void* p){
    uint32_t a;
    asm("{ .reg .u64 t; cvta.to.shared.u64 t, %1; cvt.u32.u64 %0, t; }" : "=r"(a) : "l"(p));
    return a;
}
__device__ __forceinline__ void ldm4(unsigned* r, uint32_t addr){
    asm volatile("ldmatrix.sync.aligned.m8n8.x4.shared.b16 {%0,%1,%2,%3}, [%4];"
        : "=r"(r[0]), "=r"(r[1]), "=r"(r[2]), "=r"(r[3]) : "r"(addr));
}
__device__ __forceinline__ void mma16(float* c, const unsigned* a, const unsigned* b){
    asm volatile("mma.sync.aligned.m16n8k16.row.col.f32.bf16.bf16.f32 "
        "{%0,%1,%2,%3}, {%4,%5,%6,%7}, {%8,%9}, {%0,%1,%2,%3};"
        : "+f"(c[0]), "+f"(c[1]), "+f"(c[2]), "+f"(c[3])
        : "r"(a[0]), "r"(a[1]), "r"(a[2]), "r"(a[3]), "r"(b[0]), "r"(b[1]));
}
__device__ __forceinline__ uint32_t pk2(__nv_bfloat16 a, __nv_bfloat16 b){
    return (uint32_t)__bfloat16_as_ushort(a) | ((uint32_t)__bfloat16_as_ushort(b) << 16);
}
__device__ __forceinline__ void splitStore(float4 v, char* hb, char* lb, int off){
    __nv_bfloat16 hx = __float2bfloat16_rn(v.x);
    __nv_bfloat16 hy = __float2bfloat16_rn(v.y);
    __nv_bfloat16 hz = __float2bfloat16_rn(v.z);
    __nv_bfloat16 hw = __float2bfloat16_rn(v.w);
    *(uint2*)(hb + off) = make_uint2(pk2(hx, hy), pk2(hz, hw));
    __nv_bfloat16 lx = __float2bfloat16_rn(v.x - __bfloat162float(hx));
    __nv_bfloat16 ly = __float2bfloat16_rn(v.y - __bfloat162float(hy));
    __nv_bfloat16 lz = __float2bfloat16_rn(v.z - __bfloat162float(hz));
    __nv_bfloat16 lw = __float2bfloat16_rn(v.w - __bfloat162float(hw));
    *(uint2*)(lb + off) = make_uint2(pk2(lx, ly), pk2(lz, lw));
}

// ---------------- transpose: out[C][R] = in[R][C], batched over z ----------------
__global__ void k_tr(const float* __restrict__ in, float* __restrict__ out, int R, int C){
    __shared__ float t[32][33];
    const float* ip = in  + (size_t)blockIdx.z * R * C;
    float*       op = out + (size_t)blockIdx.z * R * C;
    int bx = blockIdx.x*32, by = blockIdx.y*32;
    int tx = threadIdx.x, ty = threadIdx.y;
    #pragma unroll
    for (int i = 0; i < 32; i += 8)
        t[ty+i][tx] = ip[(size_t)(by+ty+i)*C + bx+tx];
    __syncthreads();
    #pragma unroll
    for (int i = 0; i < 32; i += 8)
        op[(size_t)(bx+ty+i)*R + by+tx] = t[tx][ty+i];
}

// ---------------- K0: precompute v_h, c_h ----------------
__global__ void k_prep(const float* __restrict__ W2, const float* __restrict__ b2,
                       const float* __restrict__ watt){
    int idx = blockIdx.x;
    const float* row = (idx < HDc) ? (W2 + (size_t)idx * Ec)
                                   : (b2 + (size_t)(idx - HDc) * Ec);
    int t = threadIdx.x;
    float4 a = ((const float4*)row)[t];
    float4 w = ((const float4*)watt)[t];
    float p = a.x*w.x + a.y*w.y + a.z*w.z + a.w*w.w;
    p = warpSum(p);
    __shared__ float sh[8];
    if ((t & 31) == 0) sh[t >> 5] = p;
    __syncthreads();
    if (t == 0){
        float r = 0.f;
        #pragma unroll
        for (int i = 0; i < 8; i++) r += sh[i];
        if (idx < HDc) g_v[idx] = r; else g_c[idx - HDc] = r;
    }
}

// ---------------- bf16-split tensor-core GEMM (mma.sync + ldmatrix) ----------------
// C[m,n] = sum_k A[m,k] * Bt[n,k]  (+ epilogue); 128x128 tile, BK=32, 256 thr,
// 8 warps 2(m) x 4(n), warp tile 64x32.
// EPI 0: tanh(acc+bias[n]); EPI 1: gelu(acc+bias[n]);
// EPI 2: acc + sum_h scores[m,h]*bias[h*Ec+n]
template<int EPI>
__global__ void __launch_bounds__(256) k_gemm_bf(
    const float* __restrict__ A,  int lda, long strA,
    const float* __restrict__ Bt, int ldb, long strB,
    float* __restrict__ C, int ldc, long strC,
    int K,
    const float* __restrict__ bias, long strBias,
    const float* __restrict__ scores)
{
    extern __shared__ __align__(16) char smem[];
    const int tid = threadIdx.x;
    const int l   = tid & 31;
    const int wm  = (tid >> 5) & 1;
    const int wn  = tid >> 6;
    const uint32_t sb = smem_u32(smem);

    const int zb = blockIdx.z;
    A  += (size_t)zb * strA;
    Bt += (size_t)zb * strB;
    C  += (size_t)zb * strC;
    const float* bi = bias + (size_t)zb * strBias;
    const int m0 = blockIdx.y * 128;
    const int n0 = blockIdx.x * 128;

    // global load mapping: 2 threads per row, 16 cols each
    const int grow = tid >> 1;
    const int gcol = (tid & 1) * 16;
    const float* Arow = A  + (size_t)(m0 + grow) * lda + gcol;
    const float* Brow = Bt + (size_t)(n0 + grow) * ldb + gcol;
    const int soff = grow * RS + gcol * 2;

    float acc[4][4][4];
    #pragma unroll
    for (int i = 0; i < 4; i++)
        #pragma unroll
        for (int j = 0; j < 4; j++)
            #pragma unroll
            for (int k = 0; k < 4; k++) acc[i][j][k] = 0.f;

    float4 ra[4], rb[4];
    #pragma unroll
    for (int j = 0; j < 4; j++){
        ra[j] = *(const float4*)(Arow + 4*j);
        rb[j] = *(const float4*)(Brow + 4*j);
    }
    {   // store stage 0
        char* st = smem;
        #pragma unroll
        for (int j = 0; j < 4; j++){
            splitStore(ra[j], st,            st + TILE_B,   soff + 8*j);
            splitStore(rb[j], st + 2*TILE_B, st + 3*TILE_B, soff + 8*j);
        }
    }
    __syncthreads();

    // ldmatrix address components
    const uint32_t aoff = (uint32_t)((wm*64 + (l & 15)) * RS + (l >> 4) * 16);
    const uint32_t boff = (uint32_t)((wn*32 + (l & 7) + ((l >> 4) & 1) * 8) * RS
                                     + ((l >> 3) & 1) * 16);

    const int nk = K >> 5;
    for (int kt = 0; kt < nk; kt++){
        const int cur = kt & 1;
        if (kt + 1 < nk){
            const float* Ap = Arow + (kt + 1) * 32;
            const float* Bp = Brow + (size_t)(kt + 1) * 32;
            #pragma unroll
            for (int j = 0; j < 4; j++){
                ra[j] = *(const float4*)(Ap + 4*j);
                rb[j] = *(const float4*)(Bp + 4*j);
            }
        }
        // compute on buffer cur
        {
            const uint32_t s0 = sb + cur * STAGE_B;
            #pragma unroll
            for (int kk = 0; kk < 2; kk++){
                const uint32_t kby = kk * 32;
                unsigned bh[4][2], bl[4][2], t4[4];
                #pragma unroll
                for (int ntp = 0; ntp < 2; ntp++){
                    ldm4(t4, s0 + 2*TILE_B + boff + ntp*16*RS + kby);
                    bh[2*ntp][0] = t4[0]; bh[2*ntp][1] = t4[1];
                    bh[2*ntp+1][0] = t4[2]; bh[2*ntp+1][1] = t4[3];
                    ldm4(t4, s0 + 3*TILE_B + boff + ntp*16*RS + kby);
                    bl[2*ntp][0] = t4[0]; bl[2*ntp][1] = t4[1];
                    bl[2*ntp+1][0] = t4[2]; bl[2*ntp+1][1] = t4[3];
                }
                #pragma unroll
                for (int mt = 0; mt < 4; mt++){
                    unsigned ah[4], al[4];
                    ldm4(ah, s0 +          aoff + mt*16*RS + kby);
                    ldm4(al, s0 + TILE_B + aoff + mt*16*RS + kby);
                    #pragma unroll
                    for (int nt = 0; nt < 4; nt++){
                        mma16(acc[mt][nt], ah, bh[nt]);
                        mma16(acc[mt][nt], al, bh[nt]);
                        mma16(acc[mt][nt], ah, bl[nt]);
                    }
                }
            }
        }
        __syncthreads();
        if (kt + 1 < nk){
            char* st = smem + (cur ^ 1) * STAGE_B;
            #pragma unroll
            for (int j = 0; j < 4; j++){
                splitStore(ra[j], st,            st + TILE_B,   soff + 8*j);
                splitStore(rb[j], st + 2*TILE_B, st + 3*TILE_B, soff + 8*j);
            }
            __syncthreads();
        }
    }

    // ---------------- epilogue ----------------
    const int lq = l >> 2;   // 0..7
    const int lr = l & 3;    // 0..3

    if (EPI == 2){
        float* scrS = (float*)smem;               // 1024 floats
        float* b2S  = (float*)(smem + 4096);      // 1024 floats
        for (int i = tid; i < 1024; i += 256)
            scrS[i] = scores[(size_t)(m0 + (i >> 3)) * 8 + (i & 7)];
        for (int i = tid; i < 1024; i += 256)
            b2S[i] = bi[(size_t)(i >> 7) * Ec + n0 + (i & 127)];
        __syncthreads();
        #pragma unroll
        for (int mt = 0; mt < 4; mt++){
            const int rl = wm*64 + mt*16 + lq;
            #pragma unroll
            for (int nt = 0; nt < 4; nt++){
                const int cl = wn*32 + nt*8 + 2*lr;
                float s0 = acc[mt][nt][0], s1 = acc[mt][nt][1];
                float s2 = acc[mt][nt][2], s3 = acc[mt][nt][3];
                #pragma unroll
                for (int hh = 0; hh < 8; hh++){
                    const float w0 = scrS[rl*8 + hh];
                    const float w1 = scrS[(rl+8)*8 + hh];
                    const float v0 = b2S[hh*128 + cl];
                    const float v1 = b2S[hh*128 + cl + 1];
                    s0 = fmaf(w0, v0, s0); s1 = fmaf(w0, v1, s1);
                    s2 = fmaf(w1, v0, s2); s3 = fmaf(w1, v1, s3);
                }
                *(float2*)(C + (size_t)(m0 + rl) * ldc + n0 + cl)     = make_float2(s0, s1);
                *(float2*)(C + (size_t)(m0 + rl + 8) * ldc + n0 + cl) = make_float2(s2, s3);
            }
        }
    } else {
        #pragma unroll
        for (int mt = 0; mt < 4; mt++){
            const int gr = m0 + wm*64 + mt*16 + lq;
            #pragma unroll
            for (int nt = 0; nt < 4; nt++){
                const int gc = n0 + wn*32 + nt*8 + 2*lr;
                const float b0 = bi[gc], b1 = bi[gc + 1];
                float v[4];
                v[0] = acc[mt][nt][0] + b0; v[1] = acc[mt][nt][1] + b1;
                v[2] = acc[mt][nt][2] + b0; v[3] = acc[mt][nt][3] + b1;
                #pragma unroll
                for (int e = 0; e < 4; e++){
                    if (EPI == 0) v[e] = tanhf(v[e]);
                    else          v[e] = 0.5f * v[e] * (1.0f + erff(v[e] * 0.70710678118654752f));
                }
                *(float2*)(C + (size_t)gr * ldc + gc)       = make_float2(v[0], v[1]);
                *(float2*)(C + (size_t)(gr + 8) * ldc + gc) = make_float2(v[2], v[3]);
            }
        }
    }
}

// ---------------- scan: 32 blocks, 32 threads; state in registers ----------------
__global__ void k_scan(const float* __restrict__ Uh, const float* __restrict__ Uz,
                       const float* __restrict__ bu, const float* __restrict__ os,
                       const float* __restrict__ lnsg, const float* __restrict__ lnsb,
                       const float* __restrict__ ffg, const float* __restrict__ ffb)
{
    const int bh = blockIdx.x;
    const int b = bh >> 3, h = bh & 7;
    const int l = threadIdx.x;

    float uh[4], uz[4], bub[4], osd[4], g1[4], bb1[4], g2[4], bb2[4];
    #pragma unroll
    for (int k = 0; k < 4; k++){
        int d = l*4 + k;
        uh[k]  = Uh[h*Dc*Dc + d*(Dc + 1)];
        uz[k]  = Uz[h*Dc*Dc + d*(Dc + 1)];
        osd[k] = os[h*Dc*Dc + d*(Dc + 1)];
        bub[k] = bu[h*Dc + d];
        g1[k]  = lnsg[d];        bb1[k] = lnsb[d];
        g2[k]  = ffg[h*Dc + d];  bb2[k] = ffb[h*Dc + d];
    }

    const float4* zp = (const float4*)g_z  + (size_t)b*Sc*256 + h*32 + l;
    float4*       op = (float4*)g_hln      + (size_t)b*Sc*256 + h*32 + l;

    float hst[4] = {0.f, 0.f, 0.f, 0.f};
    float sh [4] = {0.f, 0.f, 0.f, 0.f};
    float4 zc = *zp;

    for (int s = 0; s < Sc; s++){
        float4 zn = {0.f,0.f,0.f,0.f};
        if (s + 1 < Sc) zn = zp[(size_t)(s + 1) * 256];

        float zv[4] = {zc.x, zc.y, zc.z, zc.w};
        float hn[4];
        float s1 = 0.f, s2 = 0.f;
        #pragma unroll
        for (int k = 0; k < 4; k++){
            float t = fmaf(hst[k], uh[k], fmaf(zv[k], uz[k], bub[k]));
            float u = __fdividef(1.f, 1.f + __expf(-t));
            float v = fmaf(u, hst[k] - zv[k], zv[k]);
            hn[k] = v;
            s1 += v;
            s2 = fmaf(v, v, s2);
        }
        float t1 = 0.f, t2 = 0.f;
        #pragma unroll
        for (int k = 0; k < 4; k++){ t1 += sh[k]; t2 = fmaf(sh[k], sh[k], t2); }

        warpRed4(s1, s2, t1, t2);

        if (s > 0){
            float m2 = t1 * (1.f/Dc);
            float vr = t2 * (1.f/Dc) - m2*m2;
            float rs2 = rsqrtf(vr + EPSc);
            float4 o;
            o.x = fmaf((sh[0]-m2)*rs2, g2[0], bb2[0]);
            o.y = fmaf((sh[1]-m2)*rs2, g2[1], bb2[1]);
            o.z = fmaf((sh[2]-m2)*rs2, g2[2], bb2[2]);
            o.w = fmaf((sh[3]-m2)*rs2, g2[3], bb2[3]);
            op[(size_t)(s - 1) * 256] = o;
        }

        float m  = s1 * (1.f/Dc);
        float vr = s2 * (1.f/Dc) - m*m;
        float rs = rsqrtf(vr + EPSc);
        #pragma unroll
        for (int k = 0; k < 4; k++){
            float v = fmaf((hn[k]-m)*rs, g1[k], bb1[k]);
            hst[k] = v;
            sh[k]  = v * osd[k];
        }
        zc = zn;
    }
    {
        float t1 = 0.f, t2 = 0.f, d1 = 0.f, d2 = 0.f;
        #pragma unroll
        for (int k = 0; k < 4; k++){ t1 += sh[k]; t2 = fmaf(sh[k], sh[k], t2); }
        warpRed4(t1, t2, d1, d2);
        float m2 = t1 * (1.f/Dc);
        float vr = t2 * (1.f/Dc) - m2*m2;
        float rs2 = rsqrtf(vr + EPSc);
        float4 o;
        o.x = fmaf((sh[0]-m2)*rs2, g2[0], bb2[0]);
        o.y = fmaf((sh[1]-m2)*rs2, g2[1], bb2[1]);
        o.z = fmaf((sh[2]-m2)*rs2, g2[2], bb2[2]);
        o.w = fmaf((sh[3]-m2)*rs2, g2[3], bb2[3]);
        op[(size_t)(Sc - 1) * 256] = o;
    }
}

// ---------------- softmax over heads, scale h1 in place ----------------
__global__ void k_soft(float* __restrict__ h1, float* __restrict__ scores){
    int row = blockIdx.x;
    int t = threadIdx.x, h = t >> 5, l = t & 31;
    float* base = h1 + (size_t)row * HDc + h * Dc;
    float4 a  = ((float4*)base)[l];
    float4 vv = ((const float4*)(g_v + h * Dc))[l];
    float p = a.x*vv.x + a.y*vv.y + a.z*vv.z + a.w*vv.w;
    p = warpSum(p);
    __shared__ float lg[8];
    if (l == 0) lg[h] = p + g_c[h];
    __syncthreads();
    float mx = lg[0];
    #pragma unroll
    for (int i = 1; i < 8; i++) mx = fmaxf(mx, lg[i]);
    float den = 0.f;
    #pragma unroll
    for (int i = 0; i < 8; i++) den += __expf(lg[i] - mx);
    float sc = __expf(lg[h] - mx) / den;
    a.x *= sc; a.y *= sc; a.z *= sc; a.w *= sc;
    ((float4*)base)[l] = a;
    if (l == 0) scores[row*Hc + h] = sc;
}

// ---------------- output LayerNorm ----------------
__global__ void k_outln(float* __restrict__ out,
                        const float* __restrict__ g, const float* __restrict__ bta){
    int row = blockIdx.x;
    int t = threadIdx.x;
    float4* p = (float4*)(out + (size_t)row * Ec);
    float4 v = p[t];
    float s1 = v.x + v.y + v.z + v.w;
    float s2 = v.x*v.x + v.y*v.y + v.z*v.z + v.w*v.w;
    s1 = warpSum(s1); s2 = warpSum(s2);
    __shared__ float sh1[8], sh2[8];
    if ((t & 31) == 0){ sh1[t >> 5] = s1; sh2[t >> 5] = s2; }
    __syncthreads();
    if (t < 32){
        float a = (t < 8) ? sh1[t] : 0.f;
        float b = (t < 8) ? sh2[t] : 0.f;
        a = warpSum(a); b = warpSum(b);
        if (t == 0){ sh1[0] = a; sh2[0] = b; }
    }
    __syncthreads();
    float mean = sh1[0] * (1.f/Ec);
    float var  = sh2[0] * (1.f/Ec) - mean*mean;
    float rs = rsqrtf(var + EPSc);
    float4 gg = ((const float4*)g  )[t];
    float4 bb = ((const float4*)bta)[t];
    float4 o;
    o.x = fmaf((v.x-mean)*rs, gg.x, bb.x);
    o.y = fmaf((v.y-mean)*rs, gg.y, bb.y);
    o.z = fmaf((v.z-mean)*rs, gg.z, bb.z);
    o.w = fmaf((v.w-mean)*rs, gg.w, bb.w);
    p[t] = o;
}

// ---------------- launch ----------------
extern "C" void kernel_launch(void* const* d_in, const int* in_sizes, int n_in,
                              void* d_out, int out_size)
{
    const float* x    = (const float*)d_in[0];
    const float* Wez  = (const float*)d_in[1];
    const float* bez  = (const float*)d_in[2];
    const float* Uh   = (const float*)d_in[3];
    const float* Uz   = (const float*)d_in[4];
    const float* bu   = (const float*)d_in[5];
    const float* os   = (const float*)d_in[6];
    const float* lnsg = (const float*)d_in[7];
    const float* lnsb = (const float*)d_in[8];
    const float* ffg  = (const float*)d_in[9];
    const float* ffb  = (const float*)d_in[10];
    const float* W1   = (const float*)d_in[11];
    const float* b1   = (const float*)d_in[12];
    const float* W2   = (const float*)d_in[13];
    const float* b2   = (const float*)d_in[14];
    const float* watt = (const float*)d_in[15];
    const float* lnog = (const float*)d_in[17];
    const float* lnob = (const float*)d_in[18];
    float* out = (float*)d_out;

    float *z, *hln, *h1, *sc, *WezT, *W2T, *W1T;
    cudaGetSymbolAddress((void**)&z,    g_z);
    cudaGetSymbolAddress((void**)&hln,  g_hln);
    cudaGetSymbolAddress((void**)&h1,   g_h1);
    cudaGetSymbolAddress((void**)&sc,   g_sc);
    cudaGetSymbolAddress((void**)&WezT, g_WezT);
    cudaGetSymbolAddress((void**)&W2T,  g_W2T);
    cudaGetSymbolAddress((void**)&W1T,  g_W1T);

    cudaFuncSetAttribute(k_gemm_bf<0>, cudaFuncAttributeMaxDynamicSharedMemorySize, SMEM_DYN);
    cudaFuncSetAttribute(k_gemm_bf<1>, cudaFuncAttributeMaxDynamicSharedMemorySize, SMEM_DYN);
    cudaFuncSetAttribute(k_gemm_bf<2>, cudaFuncAttributeMaxDynamicSharedMemorySize, SMEM_DYN);

    // one-shot transposes (B operands must be [n][k])
    k_tr<<<dim3(32,32,1), dim3(32,8)>>>(Wez, WezT, Ec, HDc);
    k_tr<<<dim3(32,32,1), dim3(32,8)>>>(W2,  W2T,  HDc, Ec);
    k_tr<<<dim3(4,4,Hc),  dim3(32,8)>>>(W1,  W1T,  Dc, Dc);
    k_prep<<<HDc + Hc, 256>>>(W2, b2, watt);

    // GEMM1: z = tanh(x @ W_ez + b_ez)
    k_gemm_bf<0><<<dim3(HDc/128, BSc/128, 1), 256, SMEM_DYN>>>(
        x, Ec, 0, WezT, Ec, 0, z, HDc, 0, Ec, bez, 0, nullptr);
    // scan
    k_scan<<<32, 32>>>(Uh, Uz, bu, os, lnsg, lnsb, ffg, ffb);
    // GEMM2 per head: h1 = gelu(hln @ W1[h] + b1[h])
    k_gemm_bf<1><<<dim3(1, BSc/128, Hc), 256, SMEM_DYN>>>(
        hln, HDc, Dc, W1T, Dc, (long)Dc*Dc, h1, HDc, Dc, Dc, b1, Dc, nullptr);
    // softmax over heads
    k_soft<<<BSc, 256>>>(h1, sc);
    // GEMM3: out_pre = g @ W2_stacked + sum_h scores*b2[h]
    k_gemm_bf<2><<<dim3(Ec/128, BSc/128, 1), 256, SMEM_DYN>>>(
        h1, HDc, 0, W2T, HDc, 0, out, Ec, 0, HDc, b2, 0, sc);
    k_outln<<<BSc, 256>>>(out, lnog, lnob);
}

// round 6
// speedup vs baseline: 1.9572x; 1.9572x over previous
#include <cuda_runtime.h>
#include <math.h>
#include <stdint.h>

#define Bc 4
#define Sc 2048
#define Ec 1024
#define Hc 8
#define Dc 128
#define BSc (Bc*Sc)        // 8192 tokens
#define HDc (Hc*Dc)        // 1024
#define EPSc 1e-5f

// ---------------- scratch ----------------
__device__ __align__(16) float g_z    [BSc*HDc];
__device__ __align__(16) float g_hln  [BSc*HDc];
__device__ __align__(16) float g_h1   [BSc*HDc];
__device__ __align__(16) float g_sc   [BSc*Hc];
__device__ __align__(16) float g_v    [HDc];
__device__ __align__(16) float g_c    [Hc];
__device__ __align__(16) float g_WezT [Ec*HDc];     // [n=HD][k=E]
__device__ __align__(16) float g_W2T  [Ec*HDc];     // [n=E][k=HD]
__device__ __align__(16) float g_W1T  [Hc*Dc*Dc];   // per head [n][k]

// ---------------- helpers ----------------
__device__ __forceinline__ float warpSum(float v){
    #pragma unroll
    for (int o = 16; o; o >>= 1) v += __shfl_xor_sync(0xffffffffu, v, o);
    return v;
}
__device__ __forceinline__ void warpRed4(float& a, float& b, float& c, float& d){
    #pragma unroll
    for (int o = 16; o; o >>= 1){
        a += __shfl_xor_sync(0xffffffffu, a, o);
        b += __shfl_xor_sync(0xffffffffu, b, o);
        c += __shfl_xor_sync(0xffffffffu, c, o);
        d += __shfl_xor_sync(0xffffffffu, d, o);
    }
}
__device__ __forceinline__ float f2tf(float f){
    unsigned r; asm("cvt.rna.tf32.f32 %0, %1;" : "=r"(r) : "f"(f));
    return __uint_as_float(r);
}
__device__ __forceinline__ void mma8(float* c, const unsigned* a, const unsigned* b){
    asm volatile("mma.sync.aligned.m16n8k8.row.col.f32.tf32.tf32.f32 "
        "{%0,%1,%2,%3}, {%4,%5,%6,%7}, {%8,%9}, {%0,%1,%2,%3};"
        : "+f"(c[0]), "+f"(c[1]), "+f"(c[2]), "+f"(c[3])
        : "r"(a[0]), "r"(a[1]), "r"(a[2]), "r"(a[3]), "r"(b[0]), "r"(b[1]));
}

// ---------------- transpose: out[C][R] = in[R][C], batched over z ----------------
__global__ void k_tr(const float* __restrict__ in, float* __restrict__ out, int R, int C){
    __shared__ float t[32][33];
    const float* ip = in  + (size_t)blockIdx.z * R * C;
    float*       op = out + (size_t)blockIdx.z * R * C;
    int bx = blockIdx.x*32, by = blockIdx.y*32;
    int tx = threadIdx.x, ty = threadIdx.y;
    #pragma unroll
    for (int i = 0; i < 32; i += 8)
        t[ty+i][tx] = ip[(size_t)(by+ty+i)*C + bx+tx];
    __syncthreads();
    #pragma unroll
    for (int i = 0; i < 32; i += 8)
        op[(size_t)(bx+ty+i)*R + by+tx] = t[tx][ty+i];
}

// ---------------- K0: precompute v_h, c_h ----------------
__global__ void k_prep(const float* __restrict__ W2, const float* __restrict__ b2,
                       const float* __restrict__ watt){
    int idx = blockIdx.x;
    const float* row = (idx < HDc) ? (W2 + (size_t)idx * Ec)
                                   : (b2 + (size_t)(idx - HDc) * Ec);
    int t = threadIdx.x;
    float4 a = ((const float4*)row)[t];
    float4 w = ((const float4*)watt)[t];
    float p = a.x*w.x + a.y*w.y + a.z*w.z + a.w*w.w;
    p = warpSum(p);
    __shared__ float sh[8];
    if ((t & 31) == 0) sh[t >> 5] = p;
    __syncthreads();
    if (t == 0){
        float r = 0.f;
        #pragma unroll
        for (int i = 0; i < 8; i++) r += sh[i];
        if (idx < HDc) g_v[idx] = r; else g_c[idx - HDc] = r;
    }
}

// ---------------- TF32 tensor-core GEMM, fragment-ordered smem ----------------
// C[m,n] = sum_k A[m,k] * Bt[n,k]  (+ epilogue); 128x128 tile, BK=16, 256 thr,
// 8 warps in 2(m) x 4(n); warp tile 64x32.
// smem layout (per stage):
//   A: float4 slot per (k8, R=row/16, lane):   idx = ((k8*8+R)*32+l)*4 + j,
//      j = ((row>>3)&1) + 2*((col>>2)&1)   -> exact m16n8k8 A-fragment order
//   B: float2 slot per (k8, N8=n/8, lane):     idx = ((k8*16+N8)*32+l)*2 + j,
//      j = (col>>2)&1                       -> exact B-fragment order
// EPI 0: tanh(acc+bias[n]); EPI 1: gelu(acc+bias[n]);
// EPI 2: acc + sum_h scores[m,h]*bias[h*Ec+n]
template<int EPI>
__global__ void __launch_bounds__(256, 2) k_gemm_tc(
    const float* __restrict__ A,  int lda, long strA,
    const float* __restrict__ Bt, int ldb, long strB,
    float* __restrict__ C, int ldc, long strC,
    int K,
    const float* __restrict__ bias, long strBias,
    const float* __restrict__ scores)
{
    __shared__ float As[2][2048];
    __shared__ float Bs[2][2048];

    const int tid = threadIdx.x;
    const int l   = tid & 31;
    const int wm  = (tid >> 5) & 1;
    const int wn  = tid >> 6;

    const int zb = blockIdx.z;
    A  += (size_t)zb * strA;
    Bt += (size_t)zb * strB;
    C  += (size_t)zb * strC;
    const float* bi = bias + (size_t)zb * strBias;
    const int m0 = blockIdx.y * 128;
    const int n0 = blockIdx.x * 128;

    // producer mapping: col = tid&15, rows pr0..pr0+7
    const int pc  = tid & 15;
    const int pr0 = (tid >> 4) * 8;
    const int k8p = pc >> 3;
    const int aoffs = ((k8p*8 + (pr0>>4))*32 + (pc&3))*4 + ((pr0>>3)&1) + ((pc>>2)&1)*2;
    const int boffs = ((k8p*16 + (pr0>>3))*32 + (pc&3))*2 + ((pc>>2)&1);

    const float* Ag = A  + (size_t)(m0 + pr0) * lda + pc;
    const float* Bg = Bt + (size_t)(n0 + pr0) * ldb + pc;

    float acc[4][4][4];
    #pragma unroll
    for (int i = 0; i < 4; i++)
        #pragma unroll
        for (int j = 0; j < 4; j++)
            #pragma unroll
            for (int k = 0; k < 4; k++) acc[i][j][k] = 0.f;

    float ga[8], gb[8];
    #pragma unroll
    for (int i = 0; i < 8; i++){
        ga[i] = Ag[(size_t)i * lda];
        gb[i] = Bg[(size_t)i * ldb];
    }
    #pragma unroll
    for (int i = 0; i < 8; i++){
        As[0][aoffs + 16*i] = f2tf(ga[i]);
        Bs[0][boffs +  8*i] = f2tf(gb[i]);
    }
    __syncthreads();

    const int nk = K >> 4;
    for (int kt = 0; kt < nk; kt++){
        const int cur = kt & 1;
        if (kt + 1 < nk){
            const float* Ap = Ag + (kt + 1) * 16;
            const float* Bp = Bg + (kt + 1) * 16;
            #pragma unroll
            for (int i = 0; i < 8; i++){
                ga[i] = Ap[(size_t)i * lda];
                gb[i] = Bp[(size_t)i * ldb];
            }
        }
        // compute
        #pragma unroll
        for (int k8 = 0; k8 < 2; k8++){
            uint2 bf[4];
            #pragma unroll
            for (int nt = 0; nt < 4; nt++)
                bf[nt] = *(const uint2*)&Bs[cur][((k8*16 + wn*4 + nt)*32 + l)*2];
            #pragma unroll
            for (int mt = 0; mt < 4; mt++){
                uint4 af = *(const uint4*)&As[cur][((k8*8 + wm*4 + mt)*32 + l)*4];
                #pragma unroll
                for (int nt = 0; nt < 4; nt++)
                    mma8(acc[mt][nt], (const unsigned*)&af, (const unsigned*)&bf[nt]);
            }
        }
        __syncthreads();
        if (kt + 1 < nk){
            const int nxt = cur ^ 1;
            #pragma unroll
            for (int i = 0; i < 8; i++){
                As[nxt][aoffs + 16*i] = f2tf(ga[i]);
                Bs[nxt][boffs +  8*i] = f2tf(gb[i]);
            }
            __syncthreads();
        }
    }

    // ---------------- epilogue ----------------
    const int lq = l >> 2;   // 0..7
    const int lr = l & 3;    // 0..3

    if (EPI == 2){
        float* scrS = (float*)As;        // 1024 floats
        float* b2S  = (float*)Bs;        // 1024 floats
        for (int i = tid; i < 1024; i += 256)
            scrS[i] = scores[(size_t)(m0 + (i >> 3)) * 8 + (i & 7)];
        for (int i = tid; i < 1024; i += 256)
            b2S[i] = bi[(size_t)(i >> 7) * Ec + n0 + (i & 127)];
        __syncthreads();
        #pragma unroll
        for (int mt = 0; mt < 4; mt++){
            const int rl = wm*64 + mt*16 + lq;
            #pragma unroll
            for (int nt = 0; nt < 4; nt++){
                const int cl = wn*32 + nt*8 + 2*lr;
                float s0 = acc[mt][nt][0], s1 = acc[mt][nt][1];
                float s2 = acc[mt][nt][2], s3 = acc[mt][nt][3];
                #pragma unroll
                for (int hh = 0; hh < 8; hh++){
                    const float w0 = scrS[rl*8 + hh];
                    const float w1 = scrS[(rl+8)*8 + hh];
                    const float v0 = b2S[hh*128 + cl];
                    const float v1 = b2S[hh*128 + cl + 1];
                    s0 = fmaf(w0, v0, s0); s1 = fmaf(w0, v1, s1);
                    s2 = fmaf(w1, v0, s2); s3 = fmaf(w1, v1, s3);
                }
                *(float2*)(C + (size_t)(m0 + rl) * ldc + n0 + cl)     = make_float2(s0, s1);
                *(float2*)(C + (size_t)(m0 + rl + 8) * ldc + n0 + cl) = make_float2(s2, s3);
            }
        }
    } else {
        #pragma unroll
        for (int mt = 0; mt < 4; mt++){
            const int gr = m0 + wm*64 + mt*16 + lq;
            #pragma unroll
            for (int nt = 0; nt < 4; nt++){
                const int gc = n0 + wn*32 + nt*8 + 2*lr;
                const float b0 = bi[gc], b1 = bi[gc + 1];
                float v[4];
                v[0] = acc[mt][nt][0] + b0; v[1] = acc[mt][nt][1] + b1;
                v[2] = acc[mt][nt][2] + b0; v[3] = acc[mt][nt][3] + b1;
                #pragma unroll
                for (int e = 0; e < 4; e++){
                    if (EPI == 0) v[e] = tanhf(v[e]);
                    else          v[e] = 0.5f * v[e] * (1.0f + erff(v[e] * 0.70710678118654752f));
                }
                *(float2*)(C + (size_t)gr * ldc + gc)       = make_float2(v[0], v[1]);
                *(float2*)(C + (size_t)(gr + 8) * ldc + gc) = make_float2(v[2], v[3]);
            }
        }
    }
}

// ---------------- scan: 32 blocks, 32 threads; pipelined LN, deep z-prefetch ----------------
__global__ void k_scan(const float* __restrict__ Uh, const float* __restrict__ Uz,
                       const float* __restrict__ bu, const float* __restrict__ os,
                       const float* __restrict__ lnsg, const float* __restrict__ lnsb,
                       const float* __restrict__ ffg, const float* __restrict__ ffb)
{
    const int bh = blockIdx.x;
    const int b = bh >> 3, h = bh & 7;
    const int l = threadIdx.x;

    float uh[4], uz[4], osd[4], g1[4], bb1[4], g2[4], bb2[4], c1[4], cB[4];
    #pragma unroll
    for (int k = 0; k < 4; k++){
        int d = l*4 + k;
        uh[k]  = Uh[h*Dc*Dc + d*(Dc + 1)];
        uz[k]  = Uz[h*Dc*Dc + d*(Dc + 1)];
        osd[k] = os[h*Dc*Dc + d*(Dc + 1)];
        g1[k]  = lnsg[d];        bb1[k] = lnsb[d];
        g2[k]  = ffg[h*Dc + d];  bb2[k] = ffb[h*Dc + d];
        c1[k]  = g1[k] * uh[k];
        cB[k]  = fmaf(bb1[k], uh[k], bu[h*Dc + d]);   // bias folded with b1*uh
    }

    const float4* zp = (const float4*)g_z  + (size_t)b*Sc*256 + h*32 + l;
    float4*       op = (float4*)g_hln      + (size_t)b*Sc*256 + h*32 + l;

    // pipeline state: dc1 = (v-m)*c1, dg1 = (v-m)*g1, rs; init so that h_ln(-1)=0, t(0)=z*uz+bu
    float dc1[4], dg1[4];
    float rs = 1.f;
    #pragma unroll
    for (int k = 0; k < 4; k++){ dc1[k] = -bb1[k]*uh[k]; dg1[k] = -bb1[k]; }

    float4 z0 = zp[0];
    float4 z1 = (Sc > 1) ? zp[256]   : make_float4(0,0,0,0);
    float4 z2 = (Sc > 2) ? zp[2*256] : make_float4(0,0,0,0);
    float zpre[4];
    {
        float zv[4] = {z0.x, z0.y, z0.z, z0.w};
        #pragma unroll
        for (int k = 0; k < 4; k++) zpre[k] = fmaf(zv[k], uz[k], cB[k]);
    }

    float sh[4];

    for (int s = 0; s < Sc; s++){
        float4 z3 = make_float4(0,0,0,0);
        if (s + 3 < Sc) z3 = zp[(size_t)(s + 3) * 256];

        const float zv[4] = {z0.x, z0.y, z0.z, z0.w};
        float vv[4];
        float s1 = 0.f, s2 = 0.f, t1 = 0.f, t2 = 0.f;
        #pragma unroll
        for (int k = 0; k < 4; k++){
            float t   = fmaf(dc1[k], rs, zpre[k]);              // gate pre-activation
            float hln = fmaf(dg1[k], rs, bb1[k]);               // h_ln(s-1)
            float u   = __fdividef(1.f, 1.f + __expf(-t));
            float v   = fmaf(u, hln - zv[k], zv[k]);            // u*h + (1-u)*z
            vv[k] = v;
            s1 += v;  s2 = fmaf(v, v, s2);
            float shk = hln * osd[k];                           // shaped(s-1)
            sh[k] = shk;
            t1 += shk; t2 = fmaf(shk, shk, t2);
        }
        // next zpre while reduction runs
        float zpreN[4];
        {
            const float zn[4] = {z1.x, z1.y, z1.z, z1.w};
            #pragma unroll
            for (int k = 0; k < 4; k++) zpreN[k] = fmaf(zn[k], uz[k], cB[k]);
        }

        warpRed4(s1, s2, t1, t2);

        if (s > 0){  // finish ff-LN of step s-1
            float m2  = t1 * (1.f/Dc);
            float vr2 = t2 * (1.f/Dc) - m2*m2;
            float rs2 = rsqrtf(vr2 + EPSc);
            float4 o;
            o.x = fmaf((sh[0]-m2)*rs2, g2[0], bb2[0]);
            o.y = fmaf((sh[1]-m2)*rs2, g2[1], bb2[1]);
            o.z = fmaf((sh[2]-m2)*rs2, g2[2], bb2[2]);
            o.w = fmaf((sh[3]-m2)*rs2, g2[3], bb2[3]);
            op[(size_t)(s - 1) * 256] = o;
        }

        float m  = s1 * (1.f/Dc);
        float vr = s2 * (1.f/Dc) - m*m;
        rs = rsqrtf(vr + EPSc);
        #pragma unroll
        for (int k = 0; k < 4; k++){
            float d = vv[k] - m;
            dc1[k] = d * c1[k];
            dg1[k] = d * g1[k];
        }
        z0 = z1; z1 = z2; z2 = z3;
        #pragma unroll
        for (int k = 0; k < 4; k++) zpre[k] = zpreN[k];
    }
    // final step's ff-LN
    {
        float t1 = 0.f, t2 = 0.f, d1 = 0.f, d2 = 0.f;
        #pragma unroll
        for (int k = 0; k < 4; k++){
            float hln = fmaf(dg1[k], rs, bb1[k]);
            sh[k] = hln * osd[k];
            t1 += sh[k]; t2 = fmaf(sh[k], sh[k], t2);
        }
        warpRed4(t1, t2, d1, d2);
        float m2  = t1 * (1.f/Dc);
        float vr2 = t2 * (1.f/Dc) - m2*m2;
        float rs2 = rsqrtf(vr2 + EPSc);
        float4 o;
        o.x = fmaf((sh[0]-m2)*rs2, g2[0], bb2[0]);
        o.y = fmaf((sh[1]-m2)*rs2, g2[1], bb2[1]);
        o.z = fmaf((sh[2]-m2)*rs2, g2[2], bb2[2]);
        o.w = fmaf((sh[3]-m2)*rs2, g2[3], bb2[3]);
        op[(size_t)(Sc - 1) * 256] = o;
    }
}

// ---------------- softmax over heads, scale h1 in place ----------------
__global__ void k_soft(float* __restrict__ h1, float* __restrict__ scores){
    int row = blockIdx.x;
    int t = threadIdx.x, h = t >> 5, l = t & 31;
    float* base = h1 + (size_t)row * HDc + h * Dc;
    float4 a  = ((float4*)base)[l];
    float4 vv = ((const float4*)(g_v + h * Dc))[l];
    float p = a.x*vv.x + a.y*vv.y + a.z*vv.z + a.w*vv.w;
    p = warpSum(p);
    __shared__ float lg[8];
    if (l == 0) lg[h] = p + g_c[h];
    __syncthreads();
    float mx = lg[0];
    #pragma unroll
    for (int i = 1; i < 8; i++) mx = fmaxf(mx, lg[i]);
    float den = 0.f;
    #pragma unroll
    for (int i = 0; i < 8; i++) den += __expf(lg[i] - mx);
    float sc = __expf(lg[h] - mx) / den;
    a.x *= sc; a.y *= sc; a.z *= sc; a.w *= sc;
    ((float4*)base)[l] = a;
    if (l == 0) scores[row*Hc + h] = sc;
}

// ---------------- output LayerNorm ----------------
__global__ void k_outln(float* __restrict__ out,
                        const float* __restrict__ g, const float* __restrict__ bta){
    int row = blockIdx.x;
    int t = threadIdx.x;
    float4* p = (float4*)(out + (size_t)row * Ec);
    float4 v = p[t];
    float s1 = v.x + v.y + v.z + v.w;
    float s2 = v.x*v.x + v.y*v.y + v.z*v.z + v.w*v.w;
    s1 = warpSum(s1); s2 = warpSum(s2);
    __shared__ float sh1[8], sh2[8];
    if ((t & 31) == 0){ sh1[t >> 5] = s1; sh2[t >> 5] = s2; }
    __syncthreads();
    if (t < 32){
        float a = (t < 8) ? sh1[t] : 0.f;
        float b = (t < 8) ? sh2[t] : 0.f;
        a = warpSum(a); b = warpSum(b);
        if (t == 0){ sh1[0] = a; sh2[0] = b; }
    }
    __syncthreads();
    float mean = sh1[0] * (1.f/Ec);
    float var  = sh2[0] * (1.f/Ec) - mean*mean;
    float rs = rsqrtf(var + EPSc);
    float4 gg = ((const float4*)g  )[t];
    float4 bb = ((const float4*)bta)[t];
    float4 o;
    o.x = fmaf((v.x-mean)*rs, gg.x, bb.x);
    o.y = fmaf((v.y-mean)*rs, gg.y, bb.y);
    o.z = fmaf((v.z-mean)*rs, gg.z, bb.z);
    o.w = fmaf((v.w-mean)*rs, gg.w, bb.w);
    p[t] = o;
}

// ---------------- launch ----------------
extern "C" void kernel_launch(void* const* d_in, const int* in_sizes, int n_in,
                              void* d_out, int out_size)
{
    const float* x    = (const float*)d_in[0];
    const float* Wez  = (const float*)d_in[1];
    const float* bez  = (const float*)d_in[2];
    const float* Uh   = (const float*)d_in[3];
    const float* Uz   = (const float*)d_in[4];
    const float* bu   = (const float*)d_in[5];
    const float* os   = (const float*)d_in[6];
    const float* lnsg = (const float*)d_in[7];
    const float* lnsb = (const float*)d_in[8];
    const float* ffg  = (const float*)d_in[9];
    const float* ffb  = (const float*)d_in[10];
    const float* W1   = (const float*)d_in[11];
    const float* b1   = (const float*)d_in[12];
    const float* W2   = (const float*)d_in[13];
    const float* b2   = (const float*)d_in[14];
    const float* watt = (const float*)d_in[15];
    const float* lnog = (const float*)d_in[17];
    const float* lnob = (const float*)d_in[18];
    float* out = (float*)d_out;

    float *z, *hln, *h1, *sc, *WezT, *W2T, *W1T;
    cudaGetSymbolAddress((void**)&z,    g_z);
    cudaGetSymbolAddress((void**)&hln,  g_hln);
    cudaGetSymbolAddress((void**)&h1,   g_h1);
    cudaGetSymbolAddress((void**)&sc,   g_sc);
    cudaGetSymbolAddress((void**)&WezT, g_WezT);
    cudaGetSymbolAddress((void**)&W2T,  g_W2T);
    cudaGetSymbolAddress((void**)&W1T,  g_W1T);

    // one-shot transposes (B operands must be [n][k])
    k_tr<<<dim3(32,32,1), dim3(32,8)>>>(Wez, WezT, Ec, HDc);
    k_tr<<<dim3(32,32,1), dim3(32,8)>>>(W2,  W2T,  HDc, Ec);
    k_tr<<<dim3(4,4,Hc),  dim3(32,8)>>>(W1,  W1T,  Dc, Dc);
    k_prep<<<HDc + Hc, 256>>>(W2, b2, watt);

    // GEMM1: z = tanh(x @ W_ez + b_ez)
    k_gemm_tc<0><<<dim3(HDc/128, BSc/128, 1), 256>>>(
        x, Ec, 0, WezT, Ec, 0, z, HDc, 0, Ec, bez, 0, nullptr);
    // scan
    k_scan<<<32, 32>>>(Uh, Uz, bu, os, lnsg, lnsb, ffg, ffb);
    // GEMM2 per head: h1 = gelu(hln @ W1[h] + b1[h])
    k_gemm_tc<1><<<dim3(1, BSc/128, Hc), 256>>>(
        hln, HDc, Dc, W1T, Dc, (long)Dc*Dc, h1, HDc, Dc, Dc, b1, Dc, nullptr);
    // softmax over heads
    k_soft<<<BSc, 256>>>(h1, sc);
    // GEMM3: out_pre = g @ W2_stacked + sum_h scores*b2[h]
    k_gemm_tc<2><<<dim3(Ec/128, BSc/128, 1), 256>>>(
        h1, HDc, 0, W2T, HDc, 0, out, Ec, 0, HDc, b2, 0, sc);
    k_outln<<<BSc, 256>>>(out, lnog, lnob);
}

// round 17
// speedup vs baseline: 2.0683x; 1.0567x over previous
#include <cuda_runtime.h>
#include <math.h>
#include <stdint.h>

#define Bc 4
#define Sc 2048
#define Ec 1024
#define Hc 8
#define Dc 128
#define BSc (Bc*Sc)        // 8192 tokens
#define HDc (Hc*Dc)        // 1024
#define EPSc 1e-5f

// ---------------- scratch ----------------
__device__ __align__(16) float g_z    [BSc*HDc];
__device__ __align__(16) float g_hln  [BSc*HDc];
__device__ __align__(16) float g_h1   [BSc*HDc];
__device__ __align__(16) float g_sc   [BSc*Hc];
__device__ __align__(16) float g_lg   [BSc*Hc];
__device__ __align__(16) float g_v    [HDc];
__device__ __align__(16) float g_c    [Hc];
__device__ __align__(16) float g_WezT [Ec*HDc];     // [n=HD][k=E]
__device__ __align__(16) float g_W2T  [Ec*HDc];     // [n=E][k=HD]
__device__ __align__(16) float g_W1T  [Hc*Dc*Dc];   // per head [n][k]
__device__ int g_flag[512];                          // GEMM1 block completion flags

// ---------------- helpers ----------------
__device__ __forceinline__ float warpSum(float v){
    #pragma unroll
    for (int o = 16; o; o >>= 1) v += __shfl_xor_sync(0xffffffffu, v, o);
    return v;
}
__device__ __forceinline__ void warpRed4(float& a, float& b, float& c, float& d){
    #pragma unroll
    for (int o = 16; o; o >>= 1){
        a += __shfl_xor_sync(0xffffffffu, a, o);
        b += __shfl_xor_sync(0xffffffffu, b, o);
        c += __shfl_xor_sync(0xffffffffu, c, o);
        d += __shfl_xor_sync(0xffffffffu, d, o);
    }
}
__device__ __forceinline__ float f2tf(float f){
    unsigned r; asm("cvt.rna.tf32.f32 %0, %1;" : "=r"(r) : "f"(f));
    return __uint_as_float(r);
}
__device__ __forceinline__ void mma8(float* c, const unsigned* a, const unsigned* b){
    asm volatile("mma.sync.aligned.m16n8k8.row.col.f32.tf32.tf32.f32 "
        "{%0,%1,%2,%3}, {%4,%5,%6,%7}, {%8,%9}, {%0,%1,%2,%3};"
        : "+f"(c[0]), "+f"(c[1]), "+f"(c[2]), "+f"(c[3])
        : "r"(a[0]), "r"(a[1]), "r"(a[2]), "r"(a[3]), "r"(b[0]), "r"(b[1]));
}
__device__ __forceinline__ void waitflag(volatile int* f){
    if (!*f){ while (!*f) __nanosleep(128); }
    __threadfence();
}

// ---------------- transpose ----------------
__global__ void k_tr(const float* __restrict__ in, float* __restrict__ out, int R, int C){
    __shared__ float t[32][33];
    const float* ip = in  + (size_t)blockIdx.z * R * C;
    float*       op = out + (size_t)blockIdx.z * R * C;
    int bx = blockIdx.x*32, by = blockIdx.y*32;
    int tx = threadIdx.x, ty = threadIdx.y;
    #pragma unroll
    for (int i = 0; i < 32; i += 8)
        t[ty+i][tx] = ip[(size_t)(by+ty+i)*C + bx+tx];
    __syncthreads();
    #pragma unroll
    for (int i = 0; i < 32; i += 8)
        op[(size_t)(bx+ty+i)*R + by+tx] = t[tx][ty+i];
}

// ---------------- zero flags ----------------
__global__ void k_zero(){ g_flag[threadIdx.x] = 0; }

// ---------------- K0: precompute v_h, c_h ----------------
__global__ void k_prep(const float* __restrict__ W2, const float* __restrict__ b2,
                       const float* __restrict__ watt){
    int idx = blockIdx.x;
    const float* row = (idx < HDc) ? (W2 + (size_t)idx * Ec)
                                   : (b2 + (size_t)(idx - HDc) * Ec);
    int t = threadIdx.x;
    float4 a = ((const float4*)row)[t];
    float4 w = ((const float4*)watt)[t];
    float p = a.x*w.x + a.y*w.y + a.z*w.z + a.w*w.w;
    p = warpSum(p);
    __shared__ float sh[8];
    if ((t & 31) == 0) sh[t >> 5] = p;
    __syncthreads();
    if (t == 0){
        float r = 0.f;
        #pragma unroll
        for (int i = 0; i < 8; i++) r += sh[i];
        if (idx < HDc) g_v[idx] = r; else g_c[idx - HDc] = r;
    }
}

// ---------------- fused GEMM1 + scan ----------------
// blocks 0..31: scan role (one warp per (b,h)); blocks 32..543: GEMM1 role.
// GEMM1 block (yb, xb): yb encodes (chunk, batch): b=yb&3, c=yb>>2;
// m-tile = tokens [b*2048 + c*128, +128), n-tile = cols [xb*128, +128).
// After writing z it sets g_flag[yb*8+xb]=1. Scan (b,h) waits flag[(c*4+b)*8+h].
__global__ void __launch_bounds__(256, 2) k_fused(
    const float* __restrict__ x, const float* __restrict__ WezT,
    const float* __restrict__ bez,
    const float* __restrict__ Uh, const float* __restrict__ Uz,
    const float* __restrict__ bu, const float* __restrict__ os,
    const float* __restrict__ lnsg, const float* __restrict__ lnsb,
    const float* __restrict__ ffg, const float* __restrict__ ffb)
{
    __shared__ float As[2][2048];
    __shared__ float Bs[2][2048];

    if (blockIdx.x < 32){
        // ---------------- scan role ----------------
        if (threadIdx.x >= 32) return;
        const int bh = blockIdx.x;
        const int b = bh >> 3, h = bh & 7;
        const int l = threadIdx.x;

        float uh[4], uz[4], osd[4], g1[4], bb1[4], g2[4], bb2[4], c1[4], cB[4];
        #pragma unroll
        for (int k = 0; k < 4; k++){
            int d = l*4 + k;
            uh[k]  = Uh[h*Dc*Dc + d*(Dc + 1)];
            uz[k]  = Uz[h*Dc*Dc + d*(Dc + 1)];
            osd[k] = os[h*Dc*Dc + d*(Dc + 1)];
            g1[k]  = lnsg[d];        bb1[k] = lnsb[d];
            g2[k]  = ffg[h*Dc + d];  bb2[k] = ffb[h*Dc + d];
            c1[k]  = g1[k] * uh[k];
            cB[k]  = fmaf(bb1[k], uh[k], bu[h*Dc + d]);
        }

        const float4* zp = (const float4*)g_z  + (size_t)b*Sc*256 + h*32 + l;
        float4*       op = (float4*)g_hln      + (size_t)b*Sc*256 + h*32 + l;

        float dc1[4], dg1[4];
        float rs = 1.f;
        #pragma unroll
        for (int k = 0; k < 4; k++){ dc1[k] = -bb1[k]*uh[k]; dg1[k] = -bb1[k]; }

        waitflag(&g_flag[b*8 + h]);            // chunk 0 producer (c=0 -> yb=b)
        float4 z0 = zp[0];
        float4 z1 = zp[256];
        float4 z2 = zp[2*256];
        float zpre[4];
        {
            float zv[4] = {z0.x, z0.y, z0.z, z0.w};
            #pragma unroll
            for (int k = 0; k < 4; k++) zpre[k] = fmaf(zv[k], uz[k], cB[k]);
        }

        float sh[4];
        for (int s = 0; s < Sc; s++){
            const int sn = s + 3;
            float4 z3 = make_float4(0,0,0,0);
            if (sn < Sc){
                if ((sn & 127) == 0)
                    waitflag(&g_flag[((sn >> 7)*4 + b)*8 + h]);
                z3 = zp[(size_t)sn * 256];
            }

            const float zv[4] = {z0.x, z0.y, z0.z, z0.w};
            float vv[4];
            float s1 = 0.f, s2 = 0.f, t1 = 0.f, t2 = 0.f;
            #pragma unroll
            for (int k = 0; k < 4; k++){
                float t   = fmaf(dc1[k], rs, zpre[k]);
                float hln = fmaf(dg1[k], rs, bb1[k]);
                float u   = __fdividef(1.f, 1.f + __expf(-t));
                float v   = fmaf(u, hln - zv[k], zv[k]);
                vv[k] = v;
                s1 += v;  s2 = fmaf(v, v, s2);
                float shk = hln * osd[k];
                sh[k] = shk;
                t1 += shk; t2 = fmaf(shk, shk, t2);
            }
            float zpreN[4];
            {
                const float zn[4] = {z1.x, z1.y, z1.z, z1.w};
                #pragma unroll
                for (int k = 0; k < 4; k++) zpreN[k] = fmaf(zn[k], uz[k], cB[k]);
            }

            warpRed4(s1, s2, t1, t2);

            if (s > 0){
                float m2  = t1 * (1.f/Dc);
                float vr2 = t2 * (1.f/Dc) - m2*m2;
                float rs2 = rsqrtf(vr2 + EPSc);
                float4 o;
                o.x = fmaf((sh[0]-m2)*rs2, g2[0], bb2[0]);
                o.y = fmaf((sh[1]-m2)*rs2, g2[1], bb2[1]);
                o.z = fmaf((sh[2]-m2)*rs2, g2[2], bb2[2]);
                o.w = fmaf((sh[3]-m2)*rs2, g2[3], bb2[3]);
                op[(size_t)(s - 1) * 256] = o;
            }

            float m  = s1 * (1.f/Dc);
            float vr = s2 * (1.f/Dc) - m*m;
            rs = rsqrtf(vr + EPSc);
            #pragma unroll
            for (int k = 0; k < 4; k++){
                float d = vv[k] - m;
                dc1[k] = d * c1[k];
                dg1[k] = d * g1[k];
            }
            z0 = z1; z1 = z2; z2 = z3;
            #pragma unroll
            for (int k = 0; k < 4; k++) zpre[k] = zpreN[k];
        }
        {
            float t1 = 0.f, t2 = 0.f, d1 = 0.f, d2 = 0.f;
            #pragma unroll
            for (int k = 0; k < 4; k++){
                float hln = fmaf(dg1[k], rs, bb1[k]);
                sh[k] = hln * osd[k];
                t1 += sh[k]; t2 = fmaf(sh[k], sh[k], t2);
            }
            warpRed4(t1, t2, d1, d2);
            float m2  = t1 * (1.f/Dc);
            float vr2 = t2 * (1.f/Dc) - m2*m2;
            float rs2 = rsqrtf(vr2 + EPSc);
            float4 o;
            o.x = fmaf((sh[0]-m2)*rs2, g2[0], bb2[0]);
            o.y = fmaf((sh[1]-m2)*rs2, g2[1], bb2[1]);
            o.z = fmaf((sh[2]-m2)*rs2, g2[2], bb2[2]);
            o.w = fmaf((sh[3]-m2)*rs2, g2[3], bb2[3]);
            op[(size_t)(Sc - 1) * 256] = o;
        }
        return;
    }

    // ---------------- GEMM1 role ----------------
    const int bid = blockIdx.x - 32;
    const int xb = bid & 7, yb = bid >> 3;
    const int bb = yb & 3, cc = yb >> 2;
    const int m0 = (bb*16 + cc) * 128;
    const int n0 = xb * 128;

    const int tid = threadIdx.x;
    const int l   = tid & 31;
    const int wm  = (tid >> 5) & 1;
    const int wn  = tid >> 6;

    const int pc  = tid & 15;
    const int pr0 = (tid >> 4) * 8;
    const int k8p = pc >> 3;
    const int aoffs = ((k8p*8 + (pr0>>4))*32 + (pc&3))*4 + ((pr0>>3)&1) + ((pc>>2)&1)*2;
    const int boffs = ((k8p*16 + (pr0>>3))*32 + (pc&3))*2 + ((pc>>2)&1);

    const float* Ag = x     + (size_t)(m0 + pr0) * Ec + pc;
    const float* Bg = WezT  + (size_t)(n0 + pr0) * Ec + pc;

    float acc[4][4][4];
    #pragma unroll
    for (int i = 0; i < 4; i++)
        #pragma unroll
        for (int j = 0; j < 4; j++)
            #pragma unroll
            for (int k = 0; k < 4; k++) acc[i][j][k] = 0.f;

    float ga[8], gb[8];
    #pragma unroll
    for (int i = 0; i < 8; i++){
        ga[i] = Ag[(size_t)i * Ec];
        gb[i] = Bg[(size_t)i * Ec];
    }
    #pragma unroll
    for (int i = 0; i < 8; i++){
        As[0][aoffs + 16*i] = f2tf(ga[i]);
        Bs[0][boffs +  8*i] = f2tf(gb[i]);
    }
    __syncthreads();

    const int nk = Ec >> 4;
    for (int kt = 0; kt < nk; kt++){
        const int cur = kt & 1;
        if (kt + 1 < nk){
            const float* Ap = Ag + (kt + 1) * 16;
            const float* Bp = Bg + (kt + 1) * 16;
            #pragma unroll
            for (int i = 0; i < 8; i++){
                ga[i] = Ap[(size_t)i * Ec];
                gb[i] = Bp[(size_t)i * Ec];
            }
        }
        #pragma unroll
        for (int k8 = 0; k8 < 2; k8++){
            uint2 bf[4];
            #pragma unroll
            for (int nt = 0; nt < 4; nt++)
                bf[nt] = *(const uint2*)&Bs[cur][((k8*16 + wn*4 + nt)*32 + l)*2];
            #pragma unroll
            for (int mt = 0; mt < 4; mt++){
                uint4 af = *(const uint4*)&As[cur][((k8*8 + wm*4 + mt)*32 + l)*4];
                #pragma unroll
                for (int nt = 0; nt < 4; nt++)
                    mma8(acc[mt][nt], (const unsigned*)&af, (const unsigned*)&bf[nt]);
            }
        }
        __syncthreads();
        if (kt + 1 < nk){
            const int nxt = cur ^ 1;
            #pragma unroll
            for (int i = 0; i < 8; i++){
                As[nxt][aoffs + 16*i] = f2tf(ga[i]);
                Bs[nxt][boffs +  8*i] = f2tf(gb[i]);
            }
            __syncthreads();
        }
    }

    const int lq = l >> 2, lr = l & 3;
    #pragma unroll
    for (int mt = 0; mt < 4; mt++){
        const int gr = m0 + wm*64 + mt*16 + lq;
        #pragma unroll
        for (int nt = 0; nt < 4; nt++){
            const int gc = n0 + wn*32 + nt*8 + 2*lr;
            const float b0 = bez[gc], b1v = bez[gc + 1];
            float v[4];
            v[0] = tanhf(acc[mt][nt][0] + b0);  v[1] = tanhf(acc[mt][nt][1] + b1v);
            v[2] = tanhf(acc[mt][nt][2] + b0);  v[3] = tanhf(acc[mt][nt][3] + b1v);
            *(float2*)(g_z + (size_t)gr * HDc + gc)       = make_float2(v[0], v[1]);
            *(float2*)(g_z + (size_t)(gr + 8) * HDc + gc) = make_float2(v[2], v[3]);
        }
    }
    __syncthreads();
    if (tid == 0){
        __threadfence();
        atomicExch(&g_flag[yb*8 + xb], 1);
    }
}

// ---------------- TF32 tensor-core GEMM (EPI 1: GEMM2, EPI 2: GEMM3) ----------------
// EPI 1: gelu(acc+bias[n]) -> C; logits[row,head] = sum(gelu*v_h) -> scores(=g_lg)
// EPI 2: A scaled by scores on load; acc + sum_h scores[m,h]*bias[h*Ec+n]
template<int EPI>
__global__ void __launch_bounds__(256, 2) k_gemm_tc(
    const float* __restrict__ A,  int lda, long strA,
    const float* __restrict__ Bt, int ldb, long strB,
    float* __restrict__ C, int ldc, long strC,
    int K,
    const float* __restrict__ bias, long strBias,
    float* __restrict__ scores)
{
    __shared__ float As[2][2048];
    __shared__ float Bs[2][2048];

    const int tid = threadIdx.x;
    const int l   = tid & 31;
    const int wm  = (tid >> 5) & 1;
    const int wn  = tid >> 6;

    const int zb = blockIdx.z;
    A  += (size_t)zb * strA;
    Bt += (size_t)zb * strB;
    C  += (size_t)zb * strC;
    const float* bi = bias + (size_t)zb * strBias;
    const int m0 = blockIdx.y * 128;
    const int n0 = blockIdx.x * 128;

    const int pc  = tid & 15;
    const int pr0 = (tid >> 4) * 8;
    const int k8p = pc >> 3;
    const int aoffs = ((k8p*8 + (pr0>>4))*32 + (pc&3))*4 + ((pr0>>3)&1) + ((pc>>2)&1)*2;
    const int boffs = ((k8p*16 + (pr0>>3))*32 + (pc&3))*2 + ((pc>>2)&1);

    const float* Ag = A  + (size_t)(m0 + pr0) * lda + pc;
    const float* Bg = Bt + (size_t)(n0 + pr0) * ldb + pc;
    const float* scp = (EPI == 2) ? (scores + (size_t)(m0 + pr0) * 8) : nullptr;

    float acc[4][4][4];
    #pragma unroll
    for (int i = 0; i < 4; i++)
        #pragma unroll
        for (int j = 0; j < 4; j++)
            #pragma unroll
            for (int k = 0; k < 4; k++) acc[i][j][k] = 0.f;

    float ga[8], gb[8];
    #pragma unroll
    for (int i = 0; i < 8; i++){
        ga[i] = Ag[(size_t)i * lda];
        gb[i] = Bg[(size_t)i * ldb];
        if (EPI == 2) ga[i] *= scp[i*8];      // head 0 at kt=0
    }
    #pragma unroll
    for (int i = 0; i < 8; i++){
        As[0][aoffs + 16*i] = f2tf(ga[i]);
        Bs[0][boffs +  8*i] = f2tf(gb[i]);
    }
    __syncthreads();

    const int nk = K >> 4;
    for (int kt = 0; kt < nk; kt++){
        const int cur = kt & 1;
        if (kt + 1 < nk){
            const float* Ap = Ag + (kt + 1) * 16;
            const float* Bp = Bg + (kt + 1) * 16;
            const int hd = (kt + 1) >> 3;
            #pragma unroll
            for (int i = 0; i < 8; i++){
                ga[i] = Ap[(size_t)i * lda];
                gb[i] = Bp[(size_t)i * ldb];
                if (EPI == 2) ga[i] *= scp[i*8 + hd];
            }
        }
        #pragma unroll
        for (int k8 = 0; k8 < 2; k8++){
            uint2 bf[4];
            #pragma unroll
            for (int nt = 0; nt < 4; nt++)
                bf[nt] = *(const uint2*)&Bs[cur][((k8*16 + wn*4 + nt)*32 + l)*2];
            #pragma unroll
            for (int mt = 0; mt < 4; mt++){
                uint4 af = *(const uint4*)&As[cur][((k8*8 + wm*4 + mt)*32 + l)*4];
                #pragma unroll
                for (int nt = 0; nt < 4; nt++)
                    mma8(acc[mt][nt], (const unsigned*)&af, (const unsigned*)&bf[nt]);
            }
        }
        __syncthreads();
        if (kt + 1 < nk){
            const int nxt = cur ^ 1;
            #pragma unroll
            for (int i = 0; i < 8; i++){
                As[nxt][aoffs + 16*i] = f2tf(ga[i]);
                Bs[nxt][boffs +  8*i] = f2tf(gb[i]);
            }
            __syncthreads();
        }
    }

    // ---------------- epilogue ----------------
    const int lq = l >> 2, lr = l & 3;

    if (EPI == 2){
        float* scrS = (float*)As;
        float* b2S  = (float*)Bs;
        for (int i = tid; i < 1024; i += 256)
            scrS[i] = scores[(size_t)(m0 + (i >> 3)) * 8 + (i & 7)];
        for (int i = tid; i < 1024; i += 256)
            b2S[i] = bi[(size_t)(i >> 7) * Ec + n0 + (i & 127)];
        __syncthreads();
        #pragma unroll
        for (int mt = 0; mt < 4; mt++){
            const int rl = wm*64 + mt*16 + lq;
            #pragma unroll
            for (int nt = 0; nt < 4; nt++){
                const int cl = wn*32 + nt*8 + 2*lr;
                float s0 = acc[mt][nt][0], s1 = acc[mt][nt][1];
                float s2 = acc[mt][nt][2], s3 = acc[mt][nt][3];
                #pragma unroll
                for (int hh = 0; hh < 8; hh++){
                    const float w0 = scrS[rl*8 + hh];
                    const float w1 = scrS[(rl+8)*8 + hh];
                    const float v0 = b2S[hh*128 + cl];
                    const float v1 = b2S[hh*128 + cl + 1];
                    s0 = fmaf(w0, v0, s0); s1 = fmaf(w0, v1, s1);
                    s2 = fmaf(w1, v0, s2); s3 = fmaf(w1, v1, s3);
                }
                *(float2*)(C + (size_t)(m0 + rl) * ldc + n0 + cl)     = make_float2(s0, s1);
                *(float2*)(C + (size_t)(m0 + rl + 8) * ldc + n0 + cl) = make_float2(s2, s3);
            }
        }
    } else {
        // EPI 1: gelu + store + logits
        float* slg = (float*)As;      // [128] logit partials
        float* vsm = (float*)Bs;      // [128] v_h
        if (tid < 128){
            slg[tid] = 0.f;
            vsm[tid] = g_v[zb*128 + tid];
        }
        __syncthreads();
        #pragma unroll
        for (int mt = 0; mt < 4; mt++){
            const int rl = wm*64 + mt*16 + lq;
            const int gr = m0 + rl;
            float p0 = 0.f, p1 = 0.f;
            #pragma unroll
            for (int nt = 0; nt < 4; nt++){
                const int cl = wn*32 + nt*8 + 2*lr;
                const float b0 = bi[cl], b1v = bi[cl + 1];
                float v[4];
                v[0] = acc[mt][nt][0] + b0; v[1] = acc[mt][nt][1] + b1v;
                v[2] = acc[mt][nt][2] + b0; v[3] = acc[mt][nt][3] + b1v;
                #pragma unroll
                for (int e = 0; e < 4; e++)
                    v[e] = 0.5f * v[e] * (1.0f + erff(v[e] * 0.70710678118654752f));
                p0 = fmaf(v[0], vsm[cl], p0); p0 = fmaf(v[1], vsm[cl+1], p0);
                p1 = fmaf(v[2], vsm[cl], p1); p1 = fmaf(v[3], vsm[cl+1], p1);
                *(float2*)(C + (size_t)gr * ldc + cl)       = make_float2(v[0], v[1]);
                *(float2*)(C + (size_t)(gr + 8) * ldc + cl) = make_float2(v[2], v[3]);
            }
            atomicAdd(&slg[rl], p0);
            atomicAdd(&slg[rl + 8], p1);
        }
        __syncthreads();
        if (tid < 128)
            scores[(size_t)(m0 + tid) * 8 + zb] = slg[tid];   // scores == g_lg here
    }
}

// ---------------- tiny softmax over heads ----------------
__global__ void k_soft2(const float* __restrict__ lg, float* __restrict__ sc){
    int r = blockIdx.x * 256 + threadIdx.x;
    float v[8]; float mx = -1e30f;
    #pragma unroll
    for (int h = 0; h < 8; h++){ v[h] = lg[r*8 + h] + g_c[h]; mx = fmaxf(mx, v[h]); }
    float den = 0.f;
    #pragma unroll
    for (int h = 0; h < 8; h++){ v[h] = __expf(v[h] - mx); den += v[h]; }
    float inv = __fdividef(1.f, den);
    #pragma unroll
    for (int h = 0; h < 8; h++) sc[r*8 + h] = v[h] * inv;
}

// ---------------- output LayerNorm ----------------
__global__ void k_outln(float* __restrict__ out,
                        const float* __restrict__ g, const float* __restrict__ bta){
    int row = blockIdx.x;
    int t = threadIdx.x;
    float4* p = (float4*)(out + (size_t)row * Ec);
    float4 v = p[t];
    float s1 = v.x + v.y + v.z + v.w;
    float s2 = v.x*v.x + v.y*v.y + v.z*v.z + v.w*v.w;
    s1 = warpSum(s1); s2 = warpSum(s2);
    __shared__ float sh1[8], sh2[8];
    if ((t & 31) == 0){ sh1[t >> 5] = s1; sh2[t >> 5] = s2; }
    __syncthreads();
    if (t < 32){
        float a = (t < 8) ? sh1[t] : 0.f;
        float b = (t < 8) ? sh2[t] : 0.f;
        a = warpSum(a); b = warpSum(b);
        if (t == 0){ sh1[0] = a; sh2[0] = b; }
    }
    __syncthreads();
    float mean = sh1[0] * (1.f/Ec);
    float var  = sh2[0] * (1.f/Ec) - mean*mean;
    float rs = rsqrtf(var + EPSc);
    float4 gg = ((const float4*)g  )[t];
    float4 bb = ((const float4*)bta)[t];
    float4 o;
    o.x = fmaf((v.x-mean)*rs, gg.x, bb.x);
    o.y = fmaf((v.y-mean)*rs, gg.y, bb.y);
    o.z = fmaf((v.z-mean)*rs, gg.z, bb.z);
    o.w = fmaf((v.w-mean)*rs, gg.w, bb.w);
    p[t] = o;
}

// ---------------- launch ----------------
extern "C" void kernel_launch(void* const* d_in, const int* in_sizes, int n_in,
                              void* d_out, int out_size)
{
    const float* x    = (const float*)d_in[0];
    const float* Wez  = (const float*)d_in[1];
    const float* bez  = (const float*)d_in[2];
    const float* Uh   = (const float*)d_in[3];
    const float* Uz   = (const float*)d_in[4];
    const float* bu   = (const float*)d_in[5];
    const float* os   = (const float*)d_in[6];
    const float* lnsg = (const float*)d_in[7];
    const float* lnsb = (const float*)d_in[8];
    const float* ffg  = (const float*)d_in[9];
    const float* ffb  = (const float*)d_in[10];
    const float* W1   = (const float*)d_in[11];
    const float* b1   = (const float*)d_in[12];
    const float* W2   = (const float*)d_in[13];
    const float* b2   = (const float*)d_in[14];
    const float* watt = (const float*)d_in[15];
    const float* lnog = (const float*)d_in[17];
    const float* lnob = (const float*)d_in[18];
    float* out = (float*)d_out;

    float *hln, *h1, *sc, *lg, *WezT, *W2T, *W1T;
    cudaGetSymbolAddress((void**)&hln,  g_hln);
    cudaGetSymbolAddress((void**)&h1,   g_h1);
    cudaGetSymbolAddress((void**)&sc,   g_sc);
    cudaGetSymbolAddress((void**)&lg,   g_lg);
    cudaGetSymbolAddress((void**)&WezT, g_WezT);
    cudaGetSymbolAddress((void**)&W2T,  g_W2T);
    cudaGetSymbolAddress((void**)&W1T,  g_W1T);

    k_zero<<<1, 512>>>();
    k_tr<<<dim3(32,32,1), dim3(32,8)>>>(Wez, WezT, Ec, HDc);
    k_tr<<<dim3(32,32,1), dim3(32,8)>>>(W2,  W2T,  HDc, Ec);
    k_tr<<<dim3(4,4,Hc),  dim3(32,8)>>>(W1,  W1T,  Dc, Dc);
    k_prep<<<HDc + Hc, 256>>>(W2, b2, watt);

    // fused: GEMM1 (z = tanh(x@Wez+b)) + scan chasing it via flags
    k_fused<<<544, 256>>>(x, WezT, bez, Uh, Uz, bu, os, lnsg, lnsb, ffg, ffb);

    // GEMM2 per head: h1 = gelu(hln @ W1[h] + b1[h]); logits -> g_lg
    k_gemm_tc<1><<<dim3(1, BSc/128, Hc), 256>>>(
        hln, HDc, Dc, W1T, Dc, (long)Dc*Dc, h1, HDc, Dc, Dc, b1, Dc, lg);
    // softmax over heads
    k_soft2<<<BSc/256, 256>>>(lg, sc);
    // GEMM3: out_pre = (score*h1) @ W2_stacked + sum_h scores*b2[h]
    k_gemm_tc<2><<<dim3(Ec/128, BSc/128, 1), 256>>>(
        h1, HDc, 0, W2T, HDc, 0, out, Ec, 0, HDc, b2, 0, sc);
    k_outln<<<BSc, 256>>>(out, lnog, lnob);
}